// round 14
// baseline (speedup 1.0000x reference)
#include <cuda_runtime.h>
#include <cuda_bf16.h>
#include <cstdint>

#define NB 1024      // sequences (spatial positions)
#define NT 16        // sequence length (original batch)
#define TOK 16384    // NB*NT tokens, token = t*NB + b
#define DM 256
#define DI 512

// ---------------- scratch (__device__ globals; no allocations) ----------------
__device__ __align__(128) __nv_bfloat16 g_winT[1024 * 256];   // w_in^T  [n][k=256]
__device__ __align__(128) __nv_bfloat16 g_woutT[256 * 512];   // w_out^T [c][d=512]
__device__ __align__(128) __nv_bfloat16 g_wxT[48 * 512];      // w_xproj^T [j][d=512]
__device__ __align__(128) __nv_bfloat16 g_wdth[16 * 512];     // w_dt bf16 [r][d]
__device__ __align__(128) __nv_bfloat16 g_xnbf[TOK * DM];     // rmsnorm out, token-major [m][k]
__device__ __align__(128) __nv_bfloat16 g_uh[DI * TOK];       // pre-conv, channel-major [d][m]
__device__ __align__(128) __nv_bfloat16 g_sresh[DI * TOK];    // silu(res), channel-major
__device__ __align__(128) __nv_bfloat16 g_xmh[DI * TOK];      // post conv+silu, channel-major
__device__ __align__(128) __nv_bfloat16 g_xmbf[TOK * DI];     // same, token-major [m][d]
__device__ __align__(128) uint32_t      g_bcp[16 * TOK];      // packed bf16x2: r<8 B-pairs, r>=8 C-pairs
__device__ __align__(128) __nv_bfloat16 g_deltah[DI * TOK];   // softplus delta bf16, channel-major
__device__ __align__(128) __nv_bfloat16 g_ybf[TOK * DI];      // gated scan out, token-major

// ---------------- helpers ----------------
__device__ __forceinline__ uint32_t smem_u32(const void* p) {
    uint32_t a;
    asm("{ .reg .u64 t; cvta.to.shared.u64 t, %1; cvt.u32.u64 %0, t; }" : "=r"(a) : "l"(p));
    return a;
}
__device__ __forceinline__ float siluf(float x) { return __fdividef(x, 1.f + __expf(-x)); }
__device__ __forceinline__ float softplusf(float x) {
    return fmaxf(x, 0.f) + __logf(1.f + __expf(-fabsf(x)));
}
__device__ __forceinline__ uint32_t packbf(float a, float b) {
    __nv_bfloat162 t = __floats2bfloat162_rn(a, b);
    return *reinterpret_cast<uint32_t*>(&t);
}
__device__ __forceinline__ float2 unpackbf(uint32_t u) {
    __nv_bfloat162 t = *reinterpret_cast<__nv_bfloat162*>(&u);
    return __bfloat1622float2(t);
}

#define LDSM_X4(r0, r1, r2, r3, addr) \
    asm volatile("ldmatrix.sync.aligned.m8n8.x4.shared.b16 {%0,%1,%2,%3}, [%4];" \
                 : "=r"(r0), "=r"(r1), "=r"(r2), "=r"(r3) : "r"(addr))

__device__ __forceinline__ void mma_bf16(float* c, uint32_t a0, uint32_t a1, uint32_t a2,
                                         uint32_t a3, uint32_t b0, uint32_t b1) {
    asm volatile(
        "mma.sync.aligned.m16n8k16.row.col.f32.bf16.bf16.f32 "
        "{%0,%1,%2,%3}, {%4,%5,%6,%7}, {%8,%9}, {%0,%1,%2,%3};"
        : "+f"(c[0]), "+f"(c[1]), "+f"(c[2]), "+f"(c[3])
        : "r"(a0), "r"(a1), "r"(a2), "r"(a3), "r"(b0), "r"(b1));
}

__device__ __forceinline__ uint32_t swz(uint32_t off) { return off ^ ((off >> 3) & 0x70); }

#define CP16(dst, src) \
    asm volatile("cp.async.cg.shared.global [%0], [%1], 16;" :: "r"(dst), "l"(src))
#define CP_COMMIT() asm volatile("cp.async.commit_group;" ::: "memory")
#define CP_WAIT(n)  asm volatile("cp.async.wait_group %0;" :: "n"(n) : "memory")

template <int ROWS>
__device__ __forceinline__ void ldchunk_async(const __nv_bfloat16* __restrict__ g, int row0,
                                              int ld, int k0, uint32_t sm, int tid) {
    for (int u = tid; u < ROWS * 8; u += 256) {
        int r = u >> 3, q = u & 7;
        const void* src = g + (size_t)(row0 + r) * ld + k0 + q * 8;
        CP16(sm + swz(r * 128 + q * 16), src);
    }
}

// precomputed-offset fragment loads: addr = stage_base + (swzoff ^ kb)
#define LDA_PRE(a, stage, swzoff, kb) \
    LDSM_X4((a)[0], (a)[1], (a)[2], (a)[3], (stage) + ((swzoff) ^ (uint32_t)(kb)))
#define LDB_PRE(b0a, b0b, b1a, b1b, stage, swzoff, kb) \
    LDSM_X4(b0a, b0b, b1a, b1b, (stage) + ((swzoff) ^ (uint32_t)(kb)))

// ---------------- combined weight prep: 3 transposes + w_dt convert ----------------
__global__ __launch_bounds__(256) void k_prep(const float* __restrict__ w_in,
                                              const float* __restrict__ w_out,
                                              const float* __restrict__ w_xproj,
                                              const float* __restrict__ w_dt) {
    __shared__ float tile[32][33];
    int which = blockIdx.z;
    int tx = threadIdx.x, ty = threadIdx.y;
    if (which == 3) {
        int idx = (blockIdx.y * gridDim.x + blockIdx.x) * 256 + ty * 32 + tx;
        if (idx < 16 * 512) g_wdth[idx] = __float2bfloat16(w_dt[idx]);
        return;
    }
    const float* in = (which == 0) ? w_in : ((which == 1) ? w_out : w_xproj);
    __nv_bfloat16* out = (which == 0) ? g_winT : ((which == 1) ? g_woutT : g_wxT);
    int R = (which == 0) ? 256 : 512;
    int C = (which == 0) ? 1024 : ((which == 1) ? 256 : 48);
    int c0 = blockIdx.x * 32, r0 = blockIdx.y * 32;
    if (c0 >= C || r0 >= R) return;
#pragma unroll
    for (int i = 0; i < 4; i++) {
        int r = r0 + ty + 8 * i;
        if (r < R && c0 + tx < C) tile[ty + 8 * i][tx] = in[(size_t)r * C + c0 + tx];
    }
    __syncthreads();
#pragma unroll
    for (int i = 0; i < 4; i++) {
        int c = c0 + ty + 8 * i;
        if (c < C && r0 + tx < R)
            out[(size_t)c * R + r0 + tx] = __float2bfloat16(tile[tx][ty + 8 * i]);
    }
}

// ---------------- RMSNorm ----------------
__global__ __launch_bounds__(256) void k_rmsnorm(const float* __restrict__ feat,
                                                 const float* __restrict__ nw) {
    __shared__ float sred[8][32];
    __shared__ __align__(16) __nv_bfloat16 sX[32][264];
    int tx = threadIdx.x, ty = threadIdx.y;
    int t = blockIdx.y;
    int b = blockIdx.x * 32 + tx;
    const float* base = feat + (size_t)t * DM * NB + b;
    float v[32];
    float ss = 0.f;
#pragma unroll
    for (int i = 0; i < 32; i++) {
        float x = base[(size_t)(ty + 8 * i) * NB];
        v[i] = x;
        ss += x * x;
    }
    sred[ty][tx] = ss;
    __syncthreads();
    float tot = 0.f;
#pragma unroll
    for (int j = 0; j < 8; j++) tot += sred[j][tx];
    float sc = rsqrtf(tot * (1.f / DM) + 1e-5f);
#pragma unroll
    for (int i = 0; i < 32; i++)
        sX[tx][ty + 8 * i] = __float2bfloat16(v[i] * sc * nw[ty + 8 * i]);
    __syncthreads();
    int tid = ty * 32 + tx;
    size_t tok0 = (size_t)t * NB + blockIdx.x * 32;
    for (int u = tid; u < 32 * 32; u += 256) {
        int r = u >> 5, q = u & 31;
        *(uint4*)(g_xnbf + (tok0 + r) * DM + q * 8) = *(uint4*)&sX[r][q * 8];
    }
}

// ---------------- GEMM1 (HMMA; A preloaded, B 3-stage) — R10 proven form ----------------
__global__ __launch_bounds__(256, 2) void k_gemm1() {
    extern __shared__ __align__(1024) char sm[];
    int tid = threadIdx.x, wid = tid >> 5, lane = tid & 31;
    int wy = wid >> 2, wx = wid & 3;
    int fbase = blockIdx.y * 128, tbase = blockIdx.x * 128;
    uint32_t sbA = smem_u32(sm);
    uint32_t sbB = sbA + 65536;
    float acc[4][4][4];
#pragma unroll
    for (int i = 0; i < 4; i++)
#pragma unroll
        for (int j = 0; j < 4; j++)
#pragma unroll
            for (int q = 0; q < 4; q++) acc[i][j][q] = 0.f;

    uint32_t aoff[4], boff[2];
#pragma unroll
    for (int ft = 0; ft < 4; ft++)
        aoff[ft] = swz((uint32_t)((wy * 64 + ft * 16 + (lane & 15)) * 128 + ((lane >> 4) << 4)));
#pragma unroll
    for (int np = 0; np < 2; np++)
        boff[np] = swz((uint32_t)((wx * 32 + np * 16 + (lane & 7) + ((lane >> 4) << 3)) * 128 +
                                  (((lane >> 3) & 1) << 4)));

#pragma unroll
    for (int c = 0; c < 4; c++)
        ldchunk_async<128>(g_winT, fbase, 256, c * 64, sbA + c * 16384, tid);
    ldchunk_async<128>(g_xnbf, tbase, 256, 0, sbB, tid);
    CP_COMMIT();
    ldchunk_async<128>(g_xnbf, tbase, 256, 64, sbB + 16384, tid);
    CP_COMMIT();

    for (int kc = 0; kc < 4; kc++) {
        CP_WAIT(1);
        __syncthreads();
        if (kc + 2 < 4)
            ldchunk_async<128>(g_xnbf, tbase, 256, (kc + 2) * 64, sbB + ((kc + 2) % 3) * 16384, tid);
        CP_COMMIT();
        uint32_t aCh = sbA + kc * 16384;
        uint32_t bCur = sbB + (kc % 3) * 16384;
#pragma unroll
        for (int ks = 0; ks < 4; ks++) {
            int kb = ks * 32;
            uint32_t b[4][2];
#pragma unroll
            for (int np = 0; np < 2; np++)
                LDB_PRE(b[np * 2][0], b[np * 2][1], b[np * 2 + 1][0], b[np * 2 + 1][1],
                        bCur, boff[np], kb);
#pragma unroll
            for (int ft = 0; ft < 4; ft++) {
                uint32_t a[4];
                LDA_PRE(a, aCh, aoff[ft], kb);
#pragma unroll
                for (int nt = 0; nt < 4; nt++)
                    mma_bf16(acc[ft][nt], a[0], a[1], a[2], a[3], b[nt][0], b[nt][1]);
            }
        }
    }

    bool isRes = (fbase >= DI);
    __nv_bfloat16* base = isRes ? g_sresh : g_uh;
    int fb = isRes ? (fbase - DI) : fbase;
#pragma unroll
    for (int ft = 0; ft < 4; ft++) {
#pragma unroll
        for (int nt = 0; nt < 4; nt++) {
            float* c = acc[ft][nt];
            int f = fb + wy * 64 + ft * 16 + (lane >> 2);
            int m = tbase + wx * 32 + nt * 8 + (lane & 3) * 2;
            if (isRes) {
                *(uint32_t*)(base + (size_t)f * TOK + m)       = packbf(siluf(c[0]), siluf(c[1]));
                *(uint32_t*)(base + (size_t)(f + 8) * TOK + m) = packbf(siluf(c[2]), siluf(c[3]));
            } else {
                *(uint32_t*)(base + (size_t)f * TOK + m)       = packbf(c[0], c[1]);
                *(uint32_t*)(base + (size_t)(f + 8) * TOK + m) = packbf(c[2], c[3]);
            }
        }
    }
}

// ---------------- depthwise causal conv (k=3) + silu; vectorized, dual-layout ----------------
__global__ __launch_bounds__(256) void k_conv(const float* __restrict__ cw,
                                              const float* __restrict__ cb) {
    __shared__ __align__(16) __nv_bfloat16 sT[32][72];
    int tid = threadIdx.x;
    int dl = tid >> 3;
    int ml = (tid & 7) << 3;
    int d = blockIdx.y * 32 + dl;
    int m0 = blockIdx.x * 64 + ml;
    int t = m0 >> 10;                     // all 8 m share t (64-aligned tile)
    size_t base = (size_t)d * TOK + m0;
    float w0 = cw[d * 3 + 0], w1 = cw[d * 3 + 1], w2 = cw[d * 3 + 2], bb = cb[d];
    uint4 z = make_uint4(0, 0, 0, 0);
    uint4 c2 = *(const uint4*)(g_uh + base);
    uint4 c1 = (t >= 1) ? *(const uint4*)(g_uh + base - NB) : z;
    uint4 c0 = (t >= 2) ? *(const uint4*)(g_uh + base - 2 * NB) : z;
    const uint32_t* p2 = (const uint32_t*)&c2;
    const uint32_t* p1 = (const uint32_t*)&c1;
    const uint32_t* p0 = (const uint32_t*)&c0;
    uint32_t outw[4];
#pragma unroll
    for (int p = 0; p < 4; p++) {
        float2 a2 = unpackbf(p2[p]), a1 = unpackbf(p1[p]), a0 = unpackbf(p0[p]);
        float r0 = bb + w2 * a2.x + w1 * a1.x + w0 * a0.x;
        float r1 = bb + w2 * a2.y + w1 * a1.y + w0 * a0.y;
        outw[p] = packbf(siluf(r0), siluf(r1));
    }
    *(uint4*)(g_xmh + base) = *(uint4*)outw;
    *(uint4*)(&sT[dl][ml]) = *(uint4*)outw;
    __syncthreads();
    int r = tid >> 2, c8 = (tid & 3) << 3;
    __nv_bfloat16 vals[8];
#pragma unroll
    for (int j = 0; j < 8; j++) vals[j] = sT[c8 + j][r];
    *(uint4*)(g_xmbf + (size_t)(blockIdx.x * 64 + r) * DI + blockIdx.y * 32 + c8) = *(uint4*)vals;
}

// ---------------- xproj (HMMA) + fused dt: outputs g_bcp + g_deltah — R10 proven form ----------------
__global__ __launch_bounds__(256) void k_xproj(const float* __restrict__ b_dt) {
    extern __shared__ __align__(1024) char sm[];
    int tid = threadIdx.x, wid = tid >> 5, lane = tid & 31;
    int tbase = blockIdx.x * 128;
    uint32_t sbA = smem_u32(sm);                       // 8 chunks x 6144B = 49152
    uint32_t sbB = sbA + 49152;                        // 3 stages x 16384 -> 98304
    uint32_t sbW = sbA + 98304;                        // w_dt bf16 16x512 = 16384
    uint32_t sbBD = sbA + 114688;                      // b_dt fp32 = 2048
    float acc[3][2][4];
#pragma unroll
    for (int i = 0; i < 3; i++)
#pragma unroll
        for (int j = 0; j < 2; j++)
#pragma unroll
            for (int q = 0; q < 4; q++) acc[i][j][q] = 0.f;

    uint32_t aoff[3], boff;
#pragma unroll
    for (int ft = 0; ft < 3; ft++)
        aoff[ft] = swz((uint32_t)((ft * 16 + (lane & 15)) * 128 + ((lane >> 4) << 4)));
    boff = swz((uint32_t)((wid * 16 + (lane & 7) + ((lane >> 4) << 3)) * 128 +
                          (((lane >> 3) & 1) << 4)));

#pragma unroll
    for (int c = 0; c < 8; c++)
        ldchunk_async<48>(g_wxT, 0, 512, c * 64, sbA + c * 6144, tid);
    for (int u = tid; u < 1024; u += 256) CP16(sbW + u * 16, g_wdth + u * 8);
    for (int u = tid; u < 128; u += 256) CP16(sbBD + u * 16, b_dt + u * 4);
    ldchunk_async<128>(g_xmbf, tbase, 512, 0, sbB, tid);
    CP_COMMIT();
    ldchunk_async<128>(g_xmbf, tbase, 512, 64, sbB + 16384, tid);
    CP_COMMIT();

    for (int kc = 0; kc < 8; kc++) {
        CP_WAIT(1);
        __syncthreads();
        if (kc + 2 < 8)
            ldchunk_async<128>(g_xmbf, tbase, 512, (kc + 2) * 64, sbB + ((kc + 2) % 3) * 16384, tid);
        CP_COMMIT();
        uint32_t cur = sbB + (kc % 3) * 16384;
        uint32_t aCh = sbA + kc * 6144;
#pragma unroll
        for (int ks = 0; ks < 4; ks++) {
            int kb = ks * 32;
            uint32_t b[2][2];
            LDB_PRE(b[0][0], b[0][1], b[1][0], b[1][1], cur, boff, kb);
#pragma unroll
            for (int ft = 0; ft < 3; ft++) {
                uint32_t a[4];
                LDA_PRE(a, aCh, aoff[ft], kb);
#pragma unroll
                for (int nt = 0; nt < 2; nt++)
                    mma_bf16(acc[ft][nt], a[0], a[1], a[2], a[3], b[nt][0], b[nt][1]);
            }
        }
    }

    // stage results into smem (reuse B ring region; safe after mainloop + sync)
    __syncthreads();
    float* st = (float*)(sm + 49152);                  // [48][132]
#pragma unroll
    for (int ft = 0; ft < 3; ft++) {
#pragma unroll
        for (int nt = 0; nt < 2; nt++) {
            float* c = acc[ft][nt];
            int j = ft * 16 + (lane >> 2);
            int ml = wid * 16 + nt * 8 + (lane & 3) * 2;
            st[j * 132 + ml] = c[0];
            st[j * 132 + ml + 1] = c[1];
            st[(j + 8) * 132 + ml] = c[2];
            st[(j + 8) * 132 + ml + 1] = c[3];
        }
    }
    __syncthreads();
    // bcp: 16 packed rows (B pairs then C pairs), channel-major
    for (int v = tid; v < 16 * 128; v += 256) {
        int rr = v >> 7, mm = v & 127;
        g_bcp[(size_t)rr * TOK + tbase + mm] =
            packbf(st[(16 + 2 * rr) * 132 + mm], st[(17 + 2 * rr) * 132 + mm]);
    }
    // fused dt: delta[d][token] = softplus(b_dt[d] + sum_r st[r][token]*w_dt[r][d])
    {
        int token = tid & 63, dg = tid >> 6;            // 4 d-groups of 128
        const __nv_bfloat16* wd = (const __nv_bfloat16*)(sm + 98304);
        const float* bd = (const float*)(sm + 114688);
        float x0[16], x1[16];
#pragma unroll
        for (int r = 0; r < 16; r++) {
            x0[r] = st[r * 132 + token];
            x1[r] = st[r * 132 + token + 64];
        }
        for (int db = 0; db < 128; db += 8) {
            int d = dg * 128 + db;
            float a0[8], a1[8];
#pragma unroll
            for (int i = 0; i < 8; i++) { a0[i] = bd[d + i]; a1[i] = a0[i]; }
#pragma unroll
            for (int r = 0; r < 16; r++) {
                uint4 w4 = *(const uint4*)(wd + r * 512 + d);
                const uint32_t* wp = (const uint32_t*)&w4;
#pragma unroll
                for (int p = 0; p < 4; p++) {
                    float2 w = unpackbf(wp[p]);
                    a0[2 * p] += x0[r] * w.x;  a0[2 * p + 1] += x0[r] * w.y;
                    a1[2 * p] += x1[r] * w.x;  a1[2 * p + 1] += x1[r] * w.y;
                }
            }
#pragma unroll
            for (int i = 0; i < 8; i++) {
                g_deltah[(size_t)(d + i) * TOK + tbase + token] =
                    __float2bfloat16(softplusf(a0[i]));
                g_deltah[(size_t)(d + i) * TOK + tbase + token + 64] =
                    __float2bfloat16(softplusf(a1[i]));
            }
        }
    }
}

// ---------------- selective scan: 2 tokens/thread, 64 b x 16 d per block ----------------
__global__ __launch_bounds__(512) void k_scan(const float* __restrict__ A_log,
                                              const float* __restrict__ Dv) {
    __shared__ __align__(8) uint32_t sBC[2][16][64];
    __shared__ __nv_bfloat16 sY[2][16][68];
    int tx = threadIdx.x, ty = threadIdx.y;   // tx: token-pair 0..31, ty: d 0..15
    int tid = ty * 32 + tx;
    int b0 = blockIdx.x * 64;
    int d0 = blockIdx.y * 16;
    int d = d0 + ty;
    float A_[16];
    bool fast = true;
#pragma unroll
    for (int n = 0; n < 16; n++) {
        A_[n] = -__expf(A_log[d * 16 + n]);
        fast = fast && (fabsf(A_[n] + (float)(n + 1)) < 1e-3f * (n + 1));
    }
    float Dd = Dv[d];
    float h0[16], h1[16];
#pragma unroll
    for (int n = 0; n < 16; n++) { h0[n] = 0.f; h1[n] = 0.f; }

    for (int u = tid; u < 1024; u += 512) {
        int j = u >> 6, c = u & 63;
        sBC[0][j][c] = g_bcp[(size_t)j * TOK + b0 + c];
    }
    __syncthreads();

    for (int t = 0; t < NT; t++) {
        int cur = t & 1;
        int tokbase = t * NB + b0;
        if (t + 1 < NT) {
            for (int u = tid; u < 1024; u += 512) {
                int j = u >> 6, c = u & 63;
                sBC[cur ^ 1][j][c] = g_bcp[(size_t)j * TOK + (t + 1) * NB + b0 + c];
            }
        }
        size_t off = (size_t)d * TOK + tokbase + tx * 2;
        float2 dlt = unpackbf(*(const uint32_t*)(g_deltah + off));
        float2 xv  = unpackbf(*(const uint32_t*)(g_xmh + off));
        float dxu0 = dlt.x * xv.x, dxu1 = dlt.y * xv.y;
        float y0 = 0.f, y1 = 0.f;
        if (fast) {
            float p0 = __expf(-dlt.x), p1 = __expf(-dlt.y);
            float pn0 = 1.f, pn1 = 1.f;
#pragma unroll
            for (int r = 0; r < 8; r++) {
                uint2 Bw = *(const uint2*)&sBC[cur][r][tx * 2];
                uint2 Cw = *(const uint2*)&sBC[cur][8 + r][tx * 2];
                float2 B0 = unpackbf(Bw.x), B1 = unpackbf(Bw.y);
                float2 C0 = unpackbf(Cw.x), C1 = unpackbf(Cw.y);
                pn0 *= p0; pn1 *= p1;
                h0[2 * r] = pn0 * h0[2 * r] + dxu0 * B0.x;  y0 += h0[2 * r] * C0.x;
                h1[2 * r] = pn1 * h1[2 * r] + dxu1 * B1.x;  y1 += h1[2 * r] * C1.x;
                pn0 *= p0; pn1 *= p1;
                h0[2 * r + 1] = pn0 * h0[2 * r + 1] + dxu0 * B0.y;  y0 += h0[2 * r + 1] * C0.y;
                h1[2 * r + 1] = pn1 * h1[2 * r + 1] + dxu1 * B1.y;  y1 += h1[2 * r + 1] * C1.y;
            }
        } else {
#pragma unroll
            for (int r = 0; r < 8; r++) {
                uint2 Bw = *(const uint2*)&sBC[cur][r][tx * 2];
                uint2 Cw = *(const uint2*)&sBC[cur][8 + r][tx * 2];
                float2 B0 = unpackbf(Bw.x), B1 = unpackbf(Bw.y);
                float2 C0 = unpackbf(Cw.x), C1 = unpackbf(Cw.y);
                float e00 = __expf(dlt.x * A_[2 * r]),     e01 = __expf(dlt.x * A_[2 * r + 1]);
                float e10 = __expf(dlt.y * A_[2 * r]),     e11 = __expf(dlt.y * A_[2 * r + 1]);
                h0[2 * r] = e00 * h0[2 * r] + dxu0 * B0.x;  y0 += h0[2 * r] * C0.x;
                h1[2 * r] = e10 * h1[2 * r] + dxu1 * B1.x;  y1 += h1[2 * r] * C1.x;
                h0[2 * r + 1] = e01 * h0[2 * r + 1] + dxu0 * B0.y;  y0 += h0[2 * r + 1] * C0.y;
                h1[2 * r + 1] = e11 * h1[2 * r + 1] + dxu1 * B1.y;  y1 += h1[2 * r + 1] * C1.y;
            }
        }
        float2 sres = unpackbf(*(const uint32_t*)(g_sresh + off));
        sY[cur][ty][tx * 2]     = __float2bfloat16((y0 + xv.x * Dd) * sres.x);
        sY[cur][ty][tx * 2 + 1] = __float2bfloat16((y1 + xv.y * Dd) * sres.y);
        __syncthreads();
        int token = tid >> 3, j2 = (tid & 7) * 2;
        __nv_bfloat162 w;
        w.x = sY[cur][j2][token];
        w.y = sY[cur][j2 + 1][token];
        *(uint32_t*)(g_ybf + (size_t)(tokbase + token) * DI + d0 + j2) =
            *reinterpret_cast<uint32_t*>(&w);
    }
}

// ---------------- GEMM out (HMMA + cp.async 3-stage) ----------------
__global__ __launch_bounds__(256, 2) void k_gemmout(const float* __restrict__ feat,
                                                    float* __restrict__ out) {
    extern __shared__ __align__(1024) char sm[];
    int tid = threadIdx.x, wid = tid >> 5, lane = tid & 31;
    int wy = wid >> 2, wx = wid & 3;
    int cbase = blockIdx.y * 128, tbase = blockIdx.x * 128;
    uint32_t sb = smem_u32(sm);
    float acc[4][4][4];
#pragma unroll
    for (int i = 0; i < 4; i++)
#pragma unroll
        for (int j = 0; j < 4; j++)
#pragma unroll
            for (int q = 0; q < 4; q++) acc[i][j][q] = 0.f;

    uint32_t aoff[4], boff[2];
#pragma unroll
    for (int ft = 0; ft < 4; ft++)
        aoff[ft] = swz((uint32_t)((wy * 64 + ft * 16 + (lane & 15)) * 128 + ((lane >> 4) << 4)));
#pragma unroll
    for (int np = 0; np < 2; np++)
        boff[np] = swz((uint32_t)((wx * 32 + np * 16 + (lane & 7) + ((lane >> 4) << 3)) * 128 +
                                  (((lane >> 3) & 1) << 4)));

#pragma unroll
    for (int s = 0; s < 2; s++) {
        ldchunk_async<128>(g_woutT, cbase, 512, s * 64, sb + s * 32768, tid);
        ldchunk_async<128>(g_ybf, tbase, 512, s * 64, sb + s * 32768 + 16384, tid);
        CP_COMMIT();
    }

    for (int kc = 0; kc < 8; kc++) {
        CP_WAIT(1);
        __syncthreads();
        if (kc + 2 < 8) {
            uint32_t nxt = sb + ((kc + 2) % 3) * 32768;
            ldchunk_async<128>(g_woutT, cbase, 512, (kc + 2) * 64, nxt, tid);
            ldchunk_async<128>(g_ybf, tbase, 512, (kc + 2) * 64, nxt + 16384, tid);
        }
        CP_COMMIT();
        uint32_t cur = sb + (kc % 3) * 32768;
        uint32_t sbA = cur, sbB = cur + 16384;
#pragma unroll
        for (int ks = 0; ks < 4; ks++) {
            int kb = ks * 32;
            uint32_t b[4][2];
#pragma unroll
            for (int np = 0; np < 2; np++)
                LDB_PRE(b[np * 2][0], b[np * 2][1], b[np * 2 + 1][0], b[np * 2 + 1][1],
                        sbB, boff[np], kb);
#pragma unroll
            for (int ft = 0; ft < 4; ft++) {
                uint32_t a[4];
                LDA_PRE(a, sbA, aoff[ft], kb);
#pragma unroll
                for (int nt = 0; nt < 4; nt++)
                    mma_bf16(acc[ft][nt], a[0], a[1], a[2], a[3], b[nt][0], b[nt][1]);
            }
        }
    }

    int t = tbase >> 10;
#pragma unroll
    for (int ft = 0; ft < 4; ft++) {
#pragma unroll
        for (int nt = 0; nt < 4; nt++) {
            float* c = acc[ft][nt];
            int cc = cbase + wy * 64 + ft * 16 + (lane >> 2);
            int m = tbase + wx * 32 + nt * 8 + (lane & 3) * 2;
            int b = m & 1023;
            size_t o0 = (size_t)t * DM * NB + (size_t)cc * NB + b;
            size_t o1 = o0 + 8 * (size_t)NB;
            float2 f0 = *(const float2*)(feat + o0);
            float2 f1 = *(const float2*)(feat + o1);
            float2 v0; v0.x = c[0] + f0.x; v0.y = c[1] + f0.y;
            float2 v1; v1.x = c[2] + f1.x; v1.y = c[3] + f1.y;
            *(float2*)(out + o0) = v0;
            *(float2*)(out + o1) = v1;
        }
    }
}

extern "C" void kernel_launch(void* const* d_in, const int* in_sizes, int n_in,
                              void* d_out, int out_size) {
    const float* feature = (const float*)d_in[0];
    const float* norm_w  = (const float*)d_in[1];
    const float* w_in    = (const float*)d_in[2];
    const float* conv_w  = (const float*)d_in[3];
    const float* conv_b  = (const float*)d_in[4];
    const float* w_xproj = (const float*)d_in[5];
    const float* w_dt    = (const float*)d_in[6];
    const float* b_dt    = (const float*)d_in[7];
    const float* A_log   = (const float*)d_in[8];
    const float* Dv      = (const float*)d_in[9];
    const float* w_out   = (const float*)d_in[10];
    float* out = (float*)d_out;

    const int SMEM_G1   = 65536 + 3 * 16384;      // 114688
    const int SMEM_GOUT = 3 * 32768;
    const int SMEM_XP   = 49152 + 3 * 16384 + 16384 + 2048;  // 116736
    cudaFuncSetAttribute(k_gemm1, cudaFuncAttributeMaxDynamicSharedMemorySize, SMEM_G1);
    cudaFuncSetAttribute(k_xproj, cudaFuncAttributeMaxDynamicSharedMemorySize, SMEM_XP);
    cudaFuncSetAttribute(k_gemmout, cudaFuncAttributeMaxDynamicSharedMemorySize, SMEM_GOUT);

    k_prep<<<dim3(32, 16, 4), dim3(32, 8)>>>(w_in, w_out, w_xproj, w_dt);
    k_rmsnorm<<<dim3(32, 16), dim3(32, 8)>>>(feature, norm_w);
    k_gemm1<<<dim3(128, 8), 256, SMEM_G1>>>();
    k_conv<<<dim3(256, 16), 256>>>(conv_w, conv_b);
    k_xproj<<<dim3(128, 1), 256, SMEM_XP>>>(b_dt);
    k_scan<<<dim3(16, 32), dim3(32, 16)>>>(A_log, Dv);
    k_gemmout<<<dim3(128, 2), 256, SMEM_GOUT>>>(feature, out);
}

// round 15
// speedup vs baseline: 1.1863x; 1.1863x over previous
#include <cuda_runtime.h>
#include <cuda_bf16.h>
#include <cstdint>

#define NB 1024      // sequences (spatial positions)
#define NT 16        // sequence length (original batch)
#define TOK 16384    // NB*NT tokens, token = t*NB + b
#define DM 256
#define DI 512

// ---------------- scratch (__device__ globals; no allocations) ----------------
__device__ __align__(128) __nv_bfloat16 g_winT[1024 * 256];   // w_in^T  [n][k=256]
__device__ __align__(128) __nv_bfloat16 g_woutT[256 * 512];   // w_out^T [c][d=512]
__device__ __align__(128) __nv_bfloat16 g_wxT[48 * 512];      // w_xproj^T [j][d=512]
__device__ __align__(128) __nv_bfloat16 g_wdth[16 * 512];     // w_dt bf16 [r][d]
__device__ __align__(128) __nv_bfloat16 g_xnbf[TOK * DM];     // rmsnorm out, token-major [m][k]
__device__ __align__(128) __nv_bfloat16 g_uh[DI * TOK];       // pre-conv, channel-major [d][m]
__device__ __align__(128) __nv_bfloat16 g_sresh[DI * TOK];    // silu(res), channel-major
__device__ __align__(128) __nv_bfloat16 g_xmh[DI * TOK];      // post conv+silu, channel-major
__device__ __align__(128) __nv_bfloat16 g_xmbf[TOK * DI];     // same, token-major [m][d]
__device__ __align__(128) uint32_t      g_bcp[16 * TOK];      // packed bf16x2: r<8 B-pairs, r>=8 C-pairs
__device__ __align__(128) __nv_bfloat16 g_deltah[DI * TOK];   // softplus delta bf16, channel-major
__device__ __align__(128) __nv_bfloat16 g_ybf[TOK * DI];      // gated scan out, token-major

// ---------------- helpers ----------------
__device__ __forceinline__ uint32_t smem_u32(const void* p) {
    uint32_t a;
    asm("{ .reg .u64 t; cvta.to.shared.u64 t, %1; cvt.u32.u64 %0, t; }" : "=r"(a) : "l"(p));
    return a;
}
__device__ __forceinline__ float siluf(float x) { return __fdividef(x, 1.f + __expf(-x)); }
__device__ __forceinline__ float softplusf(float x) {
    return fmaxf(x, 0.f) + __logf(1.f + __expf(-fabsf(x)));
}
__device__ __forceinline__ uint32_t packbf(float a, float b) {
    __nv_bfloat162 t = __floats2bfloat162_rn(a, b);
    return *reinterpret_cast<uint32_t*>(&t);
}
__device__ __forceinline__ float2 unpackbf(uint32_t u) {
    __nv_bfloat162 t = *reinterpret_cast<__nv_bfloat162*>(&u);
    return __bfloat1622float2(t);
}

#define LDSM_X4(r0, r1, r2, r3, addr) \
    asm volatile("ldmatrix.sync.aligned.m8n8.x4.shared.b16 {%0,%1,%2,%3}, [%4];" \
                 : "=r"(r0), "=r"(r1), "=r"(r2), "=r"(r3) : "r"(addr))

__device__ __forceinline__ void mma_bf16(float* c, uint32_t a0, uint32_t a1, uint32_t a2,
                                         uint32_t a3, uint32_t b0, uint32_t b1) {
    asm volatile(
        "mma.sync.aligned.m16n8k16.row.col.f32.bf16.bf16.f32 "
        "{%0,%1,%2,%3}, {%4,%5,%6,%7}, {%8,%9}, {%0,%1,%2,%3};"
        : "+f"(c[0]), "+f"(c[1]), "+f"(c[2]), "+f"(c[3])
        : "r"(a0), "r"(a1), "r"(a2), "r"(a3), "r"(b0), "r"(b1));
}

__device__ __forceinline__ uint32_t swz(uint32_t off) { return off ^ ((off >> 3) & 0x70); }

#define CP16(dst, src) \
    asm volatile("cp.async.cg.shared.global [%0], [%1], 16;" :: "r"(dst), "l"(src))
#define CP_COMMIT() asm volatile("cp.async.commit_group;" ::: "memory")
#define CP_WAIT(n)  asm volatile("cp.async.wait_group %0;" :: "n"(n) : "memory")

template <int ROWS>
__device__ __forceinline__ void ldchunk_async(const __nv_bfloat16* __restrict__ g, int row0,
                                              int ld, int k0, uint32_t sm, int tid) {
    for (int u = tid; u < ROWS * 8; u += 256) {
        int r = u >> 3, q = u & 7;
        const void* src = g + (size_t)(row0 + r) * ld + k0 + q * 8;
        CP16(sm + swz(r * 128 + q * 16), src);
    }
}

// precomputed-offset fragment loads: addr = stage_base + (swzoff ^ kb)
#define LDA_PRE(a, stage, swzoff, kb) \
    LDSM_X4((a)[0], (a)[1], (a)[2], (a)[3], (stage) + ((swzoff) ^ (uint32_t)(kb)))
#define LDB_PRE(b0a, b0b, b1a, b1b, stage, swzoff, kb) \
    LDSM_X4(b0a, b0b, b1a, b1b, (stage) + ((swzoff) ^ (uint32_t)(kb)))

// ---------------- combined weight prep: 3 transposes + w_dt convert ----------------
__global__ __launch_bounds__(256) void k_prep(const float* __restrict__ w_in,
                                              const float* __restrict__ w_out,
                                              const float* __restrict__ w_xproj,
                                              const float* __restrict__ w_dt) {
    __shared__ float tile[32][33];
    int which = blockIdx.z;
    int tx = threadIdx.x, ty = threadIdx.y;
    if (which == 3) {
        int idx = (blockIdx.y * gridDim.x + blockIdx.x) * 256 + ty * 32 + tx;
        if (idx < 16 * 512) g_wdth[idx] = __float2bfloat16(w_dt[idx]);
        return;
    }
    const float* in = (which == 0) ? w_in : ((which == 1) ? w_out : w_xproj);
    __nv_bfloat16* out = (which == 0) ? g_winT : ((which == 1) ? g_woutT : g_wxT);
    int R = (which == 0) ? 256 : 512;
    int C = (which == 0) ? 1024 : ((which == 1) ? 256 : 48);
    int c0 = blockIdx.x * 32, r0 = blockIdx.y * 32;
    if (c0 >= C || r0 >= R) return;
#pragma unroll
    for (int i = 0; i < 4; i++) {
        int r = r0 + ty + 8 * i;
        if (r < R && c0 + tx < C) tile[ty + 8 * i][tx] = in[(size_t)r * C + c0 + tx];
    }
    __syncthreads();
#pragma unroll
    for (int i = 0; i < 4; i++) {
        int c = c0 + ty + 8 * i;
        if (c < C && r0 + tx < R)
            out[(size_t)c * R + r0 + tx] = __float2bfloat16(tile[tx][ty + 8 * i]);
    }
}

// ---------------- RMSNorm ----------------
__global__ __launch_bounds__(256) void k_rmsnorm(const float* __restrict__ feat,
                                                 const float* __restrict__ nw) {
    __shared__ float sred[8][32];
    __shared__ __align__(16) __nv_bfloat16 sX[32][264];
    int tx = threadIdx.x, ty = threadIdx.y;
    int t = blockIdx.y;
    int b = blockIdx.x * 32 + tx;
    const float* base = feat + (size_t)t * DM * NB + b;
    float v[32];
    float ss = 0.f;
#pragma unroll
    for (int i = 0; i < 32; i++) {
        float x = base[(size_t)(ty + 8 * i) * NB];
        v[i] = x;
        ss += x * x;
    }
    sred[ty][tx] = ss;
    __syncthreads();
    float tot = 0.f;
#pragma unroll
    for (int j = 0; j < 8; j++) tot += sred[j][tx];
    float sc = rsqrtf(tot * (1.f / DM) + 1e-5f);
#pragma unroll
    for (int i = 0; i < 32; i++)
        sX[tx][ty + 8 * i] = __float2bfloat16(v[i] * sc * nw[ty + 8 * i]);
    __syncthreads();
    int tid = ty * 32 + tx;
    size_t tok0 = (size_t)t * NB + blockIdx.x * 32;
    for (int u = tid; u < 32 * 32; u += 256) {
        int r = u >> 5, q = u & 31;
        *(uint4*)(g_xnbf + (tok0 + r) * DM + q * 8) = *(uint4*)&sX[r][q * 8];
    }
}

// ---------------- GEMM1 (HMMA; A preloaded, B 3-stage) — R10 proven form ----------------
__global__ __launch_bounds__(256, 2) void k_gemm1() {
    extern __shared__ __align__(1024) char sm[];
    int tid = threadIdx.x, wid = tid >> 5, lane = tid & 31;
    int wy = wid >> 2, wx = wid & 3;
    int fbase = blockIdx.y * 128, tbase = blockIdx.x * 128;
    uint32_t sbA = smem_u32(sm);
    uint32_t sbB = sbA + 65536;
    float acc[4][4][4];
#pragma unroll
    for (int i = 0; i < 4; i++)
#pragma unroll
        for (int j = 0; j < 4; j++)
#pragma unroll
            for (int q = 0; q < 4; q++) acc[i][j][q] = 0.f;

    uint32_t aoff[4], boff[2];
#pragma unroll
    for (int ft = 0; ft < 4; ft++)
        aoff[ft] = swz((uint32_t)((wy * 64 + ft * 16 + (lane & 15)) * 128 + ((lane >> 4) << 4)));
#pragma unroll
    for (int np = 0; np < 2; np++)
        boff[np] = swz((uint32_t)((wx * 32 + np * 16 + (lane & 7) + ((lane >> 4) << 3)) * 128 +
                                  (((lane >> 3) & 1) << 4)));

#pragma unroll
    for (int c = 0; c < 4; c++)
        ldchunk_async<128>(g_winT, fbase, 256, c * 64, sbA + c * 16384, tid);
    ldchunk_async<128>(g_xnbf, tbase, 256, 0, sbB, tid);
    CP_COMMIT();
    ldchunk_async<128>(g_xnbf, tbase, 256, 64, sbB + 16384, tid);
    CP_COMMIT();

    for (int kc = 0; kc < 4; kc++) {
        CP_WAIT(1);
        __syncthreads();
        if (kc + 2 < 4)
            ldchunk_async<128>(g_xnbf, tbase, 256, (kc + 2) * 64, sbB + ((kc + 2) % 3) * 16384, tid);
        CP_COMMIT();
        uint32_t aCh = sbA + kc * 16384;
        uint32_t bCur = sbB + (kc % 3) * 16384;
#pragma unroll
        for (int ks = 0; ks < 4; ks++) {
            int kb = ks * 32;
            uint32_t b[4][2];
#pragma unroll
            for (int np = 0; np < 2; np++)
                LDB_PRE(b[np * 2][0], b[np * 2][1], b[np * 2 + 1][0], b[np * 2 + 1][1],
                        bCur, boff[np], kb);
#pragma unroll
            for (int ft = 0; ft < 4; ft++) {
                uint32_t a[4];
                LDA_PRE(a, aCh, aoff[ft], kb);
#pragma unroll
                for (int nt = 0; nt < 4; nt++)
                    mma_bf16(acc[ft][nt], a[0], a[1], a[2], a[3], b[nt][0], b[nt][1]);
            }
        }
    }

    bool isRes = (fbase >= DI);
    __nv_bfloat16* base = isRes ? g_sresh : g_uh;
    int fb = isRes ? (fbase - DI) : fbase;
#pragma unroll
    for (int ft = 0; ft < 4; ft++) {
#pragma unroll
        for (int nt = 0; nt < 4; nt++) {
            float* c = acc[ft][nt];
            int f = fb + wy * 64 + ft * 16 + (lane >> 2);
            int m = tbase + wx * 32 + nt * 8 + (lane & 3) * 2;
            if (isRes) {
                *(uint32_t*)(base + (size_t)f * TOK + m)       = packbf(siluf(c[0]), siluf(c[1]));
                *(uint32_t*)(base + (size_t)(f + 8) * TOK + m) = packbf(siluf(c[2]), siluf(c[3]));
            } else {
                *(uint32_t*)(base + (size_t)f * TOK + m)       = packbf(c[0], c[1]);
                *(uint32_t*)(base + (size_t)(f + 8) * TOK + m) = packbf(c[2], c[3]);
            }
        }
    }
}

// ---------------- depthwise causal conv (k=3) + silu; vectorized, dual-layout ----------------
__global__ __launch_bounds__(256) void k_conv(const float* __restrict__ cw,
                                              const float* __restrict__ cb) {
    __shared__ __align__(16) __nv_bfloat16 sT[32][72];
    int tid = threadIdx.x;
    int dl = tid >> 3;
    int ml = (tid & 7) << 3;
    int d = blockIdx.y * 32 + dl;
    int m0 = blockIdx.x * 64 + ml;
    int t = m0 >> 10;                     // all 8 m share t (64-aligned tile)
    size_t base = (size_t)d * TOK + m0;
    float w0 = cw[d * 3 + 0], w1 = cw[d * 3 + 1], w2 = cw[d * 3 + 2], bb = cb[d];
    uint4 z = make_uint4(0, 0, 0, 0);
    uint4 c2 = *(const uint4*)(g_uh + base);
    uint4 c1 = (t >= 1) ? *(const uint4*)(g_uh + base - NB) : z;
    uint4 c0 = (t >= 2) ? *(const uint4*)(g_uh + base - 2 * NB) : z;
    const uint32_t* p2 = (const uint32_t*)&c2;
    const uint32_t* p1 = (const uint32_t*)&c1;
    const uint32_t* p0 = (const uint32_t*)&c0;
    uint32_t outw[4];
#pragma unroll
    for (int p = 0; p < 4; p++) {
        float2 a2 = unpackbf(p2[p]), a1 = unpackbf(p1[p]), a0 = unpackbf(p0[p]);
        float r0 = bb + w2 * a2.x + w1 * a1.x + w0 * a0.x;
        float r1 = bb + w2 * a2.y + w1 * a1.y + w0 * a0.y;
        outw[p] = packbf(siluf(r0), siluf(r1));
    }
    *(uint4*)(g_xmh + base) = *(uint4*)outw;
    *(uint4*)(&sT[dl][ml]) = *(uint4*)outw;
    __syncthreads();
    int r = tid >> 2, c8 = (tid & 3) << 3;
    __nv_bfloat16 vals[8];
#pragma unroll
    for (int j = 0; j < 8; j++) vals[j] = sT[c8 + j][r];
    *(uint4*)(g_xmbf + (size_t)(blockIdx.x * 64 + r) * DI + blockIdx.y * 32 + c8) = *(uint4*)vals;
}

// ---------------- xproj (HMMA) + fused dt: outputs g_bcp + g_deltah — R10 proven form ----------------
__global__ __launch_bounds__(256) void k_xproj(const float* __restrict__ b_dt) {
    extern __shared__ __align__(1024) char sm[];
    int tid = threadIdx.x, wid = tid >> 5, lane = tid & 31;
    int tbase = blockIdx.x * 128;
    uint32_t sbA = smem_u32(sm);                       // 8 chunks x 6144B = 49152
    uint32_t sbB = sbA + 49152;                        // 3 stages x 16384 -> 98304
    uint32_t sbW = sbA + 98304;                        // w_dt bf16 16x512 = 16384
    uint32_t sbBD = sbA + 114688;                      // b_dt fp32 = 2048
    float acc[3][2][4];
#pragma unroll
    for (int i = 0; i < 3; i++)
#pragma unroll
        for (int j = 0; j < 2; j++)
#pragma unroll
            for (int q = 0; q < 4; q++) acc[i][j][q] = 0.f;

    uint32_t aoff[3], boff;
#pragma unroll
    for (int ft = 0; ft < 3; ft++)
        aoff[ft] = swz((uint32_t)((ft * 16 + (lane & 15)) * 128 + ((lane >> 4) << 4)));
    boff = swz((uint32_t)((wid * 16 + (lane & 7) + ((lane >> 4) << 3)) * 128 +
                          (((lane >> 3) & 1) << 4)));

#pragma unroll
    for (int c = 0; c < 8; c++)
        ldchunk_async<48>(g_wxT, 0, 512, c * 64, sbA + c * 6144, tid);
    for (int u = tid; u < 1024; u += 256) CP16(sbW + u * 16, g_wdth + u * 8);
    for (int u = tid; u < 128; u += 256) CP16(sbBD + u * 16, b_dt + u * 4);
    ldchunk_async<128>(g_xmbf, tbase, 512, 0, sbB, tid);
    CP_COMMIT();
    ldchunk_async<128>(g_xmbf, tbase, 512, 64, sbB + 16384, tid);
    CP_COMMIT();

    for (int kc = 0; kc < 8; kc++) {
        CP_WAIT(1);
        __syncthreads();
        if (kc + 2 < 8)
            ldchunk_async<128>(g_xmbf, tbase, 512, (kc + 2) * 64, sbB + ((kc + 2) % 3) * 16384, tid);
        CP_COMMIT();
        uint32_t cur = sbB + (kc % 3) * 16384;
        uint32_t aCh = sbA + kc * 6144;
#pragma unroll
        for (int ks = 0; ks < 4; ks++) {
            int kb = ks * 32;
            uint32_t b[2][2];
            LDB_PRE(b[0][0], b[0][1], b[1][0], b[1][1], cur, boff, kb);
#pragma unroll
            for (int ft = 0; ft < 3; ft++) {
                uint32_t a[4];
                LDA_PRE(a, aCh, aoff[ft], kb);
#pragma unroll
                for (int nt = 0; nt < 2; nt++)
                    mma_bf16(acc[ft][nt], a[0], a[1], a[2], a[3], b[nt][0], b[nt][1]);
            }
        }
    }

    // stage results into smem (reuse B ring region; safe after mainloop + sync)
    __syncthreads();
    float* st = (float*)(sm + 49152);                  // [48][132]
#pragma unroll
    for (int ft = 0; ft < 3; ft++) {
#pragma unroll
        for (int nt = 0; nt < 2; nt++) {
            float* c = acc[ft][nt];
            int j = ft * 16 + (lane >> 2);
            int ml = wid * 16 + nt * 8 + (lane & 3) * 2;
            st[j * 132 + ml] = c[0];
            st[j * 132 + ml + 1] = c[1];
            st[(j + 8) * 132 + ml] = c[2];
            st[(j + 8) * 132 + ml + 1] = c[3];
        }
    }
    __syncthreads();
    // bcp: 16 packed rows (B pairs then C pairs), channel-major
    for (int v = tid; v < 16 * 128; v += 256) {
        int rr = v >> 7, mm = v & 127;
        g_bcp[(size_t)rr * TOK + tbase + mm] =
            packbf(st[(16 + 2 * rr) * 132 + mm], st[(17 + 2 * rr) * 132 + mm]);
    }
    // fused dt: delta[d][token] = softplus(b_dt[d] + sum_r st[r][token]*w_dt[r][d])
    {
        int token = tid & 63, dg = tid >> 6;            // 4 d-groups of 128
        const __nv_bfloat16* wd = (const __nv_bfloat16*)(sm + 98304);
        const float* bd = (const float*)(sm + 114688);
        float x0[16], x1[16];
#pragma unroll
        for (int r = 0; r < 16; r++) {
            x0[r] = st[r * 132 + token];
            x1[r] = st[r * 132 + token + 64];
        }
        for (int db = 0; db < 128; db += 8) {
            int d = dg * 128 + db;
            float a0[8], a1[8];
#pragma unroll
            for (int i = 0; i < 8; i++) { a0[i] = bd[d + i]; a1[i] = a0[i]; }
#pragma unroll
            for (int r = 0; r < 16; r++) {
                uint4 w4 = *(const uint4*)(wd + r * 512 + d);
                const uint32_t* wp = (const uint32_t*)&w4;
#pragma unroll
                for (int p = 0; p < 4; p++) {
                    float2 w = unpackbf(wp[p]);
                    a0[2 * p] += x0[r] * w.x;  a0[2 * p + 1] += x0[r] * w.y;
                    a1[2 * p] += x1[r] * w.x;  a1[2 * p + 1] += x1[r] * w.y;
                }
            }
#pragma unroll
            for (int i = 0; i < 8; i++) {
                g_deltah[(size_t)(d + i) * TOK + tbase + token] =
                    __float2bfloat16(softplusf(a0[i]));
                g_deltah[(size_t)(d + i) * TOK + tbase + token + 64] =
                    __float2bfloat16(softplusf(a1[i]));
            }
        }
    }
}

// ---------------- selective scan + D-skip + silu gate (16 d x 32 b, 1 sync/t) ----------------
__global__ __launch_bounds__(512) void k_scan(const float* __restrict__ A_log,
                                              const float* __restrict__ Dv) {
    __shared__ uint32_t sBC[2][16][32];
    __shared__ __nv_bfloat16 sY[2][16][32];
    int tx = threadIdx.x, ty = threadIdx.y;
    int tid = ty * 32 + tx;
    int b0 = blockIdx.x * 32;
    int d0 = blockIdx.y * 16;
    int d = d0 + ty;
    float A_[16];
    bool fast = true;
#pragma unroll
    for (int n = 0; n < 16; n++) {
        A_[n] = -__expf(A_log[d * 16 + n]);
        fast = fast && (fabsf(A_[n] + (float)(n + 1)) < 1e-3f * (n + 1));
    }
    float Dd = Dv[d];
    float h[16];
#pragma unroll
    for (int n = 0; n < 16; n++) h[n] = 0.f;

    int j0 = tid >> 5, c0 = tid & 31;
    sBC[0][j0][c0] = g_bcp[(size_t)j0 * TOK + b0 + c0];
    __syncthreads();

    for (int t = 0; t < NT; t++) {
        int cur = t & 1;
        int tokbase = t * NB + b0;
        if (t + 1 < NT)
            sBC[cur ^ 1][j0][c0] = g_bcp[(size_t)j0 * TOK + (t + 1) * NB + b0 + c0];

        size_t off = (size_t)d * TOK + tokbase + tx;
        float dlt = __bfloat162float(g_deltah[off]);
        float xv = __bfloat162float(g_xmh[off]);
        float dxu = dlt * xv;
        float y = 0.f;
        if (fast) {
            float p = __expf(-dlt), pn = 1.f;
#pragma unroll
            for (int r = 0; r < 8; r++) {
                float2 Bp = unpackbf(sBC[cur][r][tx]);
                float2 Cp = unpackbf(sBC[cur][8 + r][tx]);
                pn *= p;
                h[2 * r] = pn * h[2 * r] + dxu * Bp.x;
                y += h[2 * r] * Cp.x;
                pn *= p;
                h[2 * r + 1] = pn * h[2 * r + 1] + dxu * Bp.y;
                y += h[2 * r + 1] * Cp.y;
            }
        } else {
#pragma unroll
            for (int r = 0; r < 8; r++) {
                float2 Bp = unpackbf(sBC[cur][r][tx]);
                float2 Cp = unpackbf(sBC[cur][8 + r][tx]);
                float dA0 = __expf(dlt * A_[2 * r]);
                float dA1 = __expf(dlt * A_[2 * r + 1]);
                h[2 * r] = dA0 * h[2 * r] + dxu * Bp.x;
                y += h[2 * r] * Cp.x;
                h[2 * r + 1] = dA1 * h[2 * r + 1] + dxu * Bp.y;
                y += h[2 * r + 1] * Cp.y;
            }
        }
        float sres = __bfloat162float(g_sresh[off]);
        sY[cur][ty][tx] = __float2bfloat16((y + xv * Dd) * sres);
        __syncthreads();
        int bl = tid >> 4, j = tid & 15;
        g_ybf[(size_t)(tokbase + bl) * DI + d0 + j] = sY[cur][j][bl];
    }
}

// ---------------- GEMM out (HMMA + cp.async 3-stage) ----------------
__global__ __launch_bounds__(256, 2) void k_gemmout(const float* __restrict__ feat,
                                                    float* __restrict__ out) {
    extern __shared__ __align__(1024) char sm[];
    int tid = threadIdx.x, wid = tid >> 5, lane = tid & 31;
    int wy = wid >> 2, wx = wid & 3;
    int cbase = blockIdx.y * 128, tbase = blockIdx.x * 128;
    uint32_t sb = smem_u32(sm);
    float acc[4][4][4];
#pragma unroll
    for (int i = 0; i < 4; i++)
#pragma unroll
        for (int j = 0; j < 4; j++)
#pragma unroll
            for (int q = 0; q < 4; q++) acc[i][j][q] = 0.f;

    uint32_t aoff[4], boff[2];
#pragma unroll
    for (int ft = 0; ft < 4; ft++)
        aoff[ft] = swz((uint32_t)((wy * 64 + ft * 16 + (lane & 15)) * 128 + ((lane >> 4) << 4)));
#pragma unroll
    for (int np = 0; np < 2; np++)
        boff[np] = swz((uint32_t)((wx * 32 + np * 16 + (lane & 7) + ((lane >> 4) << 3)) * 128 +
                                  (((lane >> 3) & 1) << 4)));

#pragma unroll
    for (int s = 0; s < 2; s++) {
        ldchunk_async<128>(g_woutT, cbase, 512, s * 64, sb + s * 32768, tid);
        ldchunk_async<128>(g_ybf, tbase, 512, s * 64, sb + s * 32768 + 16384, tid);
        CP_COMMIT();
    }

    for (int kc = 0; kc < 8; kc++) {
        CP_WAIT(1);
        __syncthreads();
        if (kc + 2 < 8) {
            uint32_t nxt = sb + ((kc + 2) % 3) * 32768;
            ldchunk_async<128>(g_woutT, cbase, 512, (kc + 2) * 64, nxt, tid);
            ldchunk_async<128>(g_ybf, tbase, 512, (kc + 2) * 64, nxt + 16384, tid);
        }
        CP_COMMIT();
        uint32_t cur = sb + (kc % 3) * 32768;
        uint32_t sbA = cur, sbB = cur + 16384;
#pragma unroll
        for (int ks = 0; ks < 4; ks++) {
            int kb = ks * 32;
            uint32_t b[4][2];
#pragma unroll
            for (int np = 0; np < 2; np++)
                LDB_PRE(b[np * 2][0], b[np * 2][1], b[np * 2 + 1][0], b[np * 2 + 1][1],
                        sbB, boff[np], kb);
#pragma unroll
            for (int ft = 0; ft < 4; ft++) {
                uint32_t a[4];
                LDA_PRE(a, sbA, aoff[ft], kb);
#pragma unroll
                for (int nt = 0; nt < 4; nt++)
                    mma_bf16(acc[ft][nt], a[0], a[1], a[2], a[3], b[nt][0], b[nt][1]);
            }
        }
    }

    int t = tbase >> 10;
#pragma unroll
    for (int ft = 0; ft < 4; ft++) {
#pragma unroll
        for (int nt = 0; nt < 4; nt++) {
            float* c = acc[ft][nt];
            int cc = cbase + wy * 64 + ft * 16 + (lane >> 2);
            int m = tbase + wx * 32 + nt * 8 + (lane & 3) * 2;
            int b = m & 1023;
            size_t o0 = (size_t)t * DM * NB + (size_t)cc * NB + b;
            size_t o1 = o0 + 8 * (size_t)NB;
            float2 f0 = *(const float2*)(feat + o0);
            float2 f1 = *(const float2*)(feat + o1);
            float2 v0; v0.x = c[0] + f0.x; v0.y = c[1] + f0.y;
            float2 v1; v1.x = c[2] + f1.x; v1.y = c[3] + f1.y;
            *(float2*)(out + o0) = v0;
            *(float2*)(out + o1) = v1;
        }
    }
}

extern "C" void kernel_launch(void* const* d_in, const int* in_sizes, int n_in,
                              void* d_out, int out_size) {
    const float* feature = (const float*)d_in[0];
    const float* norm_w  = (const float*)d_in[1];
    const float* w_in    = (const float*)d_in[2];
    const float* conv_w  = (const float*)d_in[3];
    const float* conv_b  = (const float*)d_in[4];
    const float* w_xproj = (const float*)d_in[5];
    const float* w_dt    = (const float*)d_in[6];
    const float* b_dt    = (const float*)d_in[7];
    const float* A_log   = (const float*)d_in[8];
    const float* Dv      = (const float*)d_in[9];
    const float* w_out   = (const float*)d_in[10];
    float* out = (float*)d_out;

    const int SMEM_G1   = 65536 + 3 * 16384;      // 114688
    const int SMEM_GOUT = 3 * 32768;
    const int SMEM_XP   = 49152 + 3 * 16384 + 16384 + 2048;  // 116736
    cudaFuncSetAttribute(k_gemm1, cudaFuncAttributeMaxDynamicSharedMemorySize, SMEM_G1);
    cudaFuncSetAttribute(k_xproj, cudaFuncAttributeMaxDynamicSharedMemorySize, SMEM_XP);
    cudaFuncSetAttribute(k_gemmout, cudaFuncAttributeMaxDynamicSharedMemorySize, SMEM_GOUT);

    k_prep<<<dim3(32, 16, 4), dim3(32, 8)>>>(w_in, w_out, w_xproj, w_dt);
    k_rmsnorm<<<dim3(32, 16), dim3(32, 8)>>>(feature, norm_w);
    k_gemm1<<<dim3(128, 8), 256, SMEM_G1>>>();
    k_conv<<<dim3(256, 16), 256>>>(conv_w, conv_b);
    k_xproj<<<dim3(128, 1), 256, SMEM_XP>>>(b_dt);
    k_scan<<<dim3(32, 32), dim3(32, 16)>>>(A_log, Dv);
    k_gemmout<<<dim3(128, 2), 256, SMEM_GOUT>>>(feature, out);
}